// round 4
// baseline (speedup 1.0000x reference)
#include <cuda_runtime.h>
#include <cstdint>

// Problem constants (fixed shapes from reference)
#define B_  32
#define S_  512
#define H_  768
#define P_  76
#define K_  64
#define E_  768
#define M_  (B_ * P_)     // 2432 rows

#define BM 128
#define BN 128
#define BK 16

// Scratch
__device__ float g_lm[M_ * E_];          // 7.1 MB pre-LN dense output
__device__ int   g_c64;                  // candidate_sets stored as int64? (set by GEMM CTA 0)

// ---------------------------------------------------------------------------
// Kernel 1: gathered-A SGEMM via packed fp32x2 FMA (FFMA2, 2x FFMA rate).
// 128x128 tile, 6 x 19 = 114 CTAs -> exactly one wave on 148 SMs.
// 256 threads, 8-row x 8-col microtile; accumulators are f32x2 over ROW pairs
// (A pairs load contiguously from smem; B scalars duplicated via mov.b64).
// Double-buffered smem + register prefetch; inline index-dtype detection.
// ---------------------------------------------------------------------------
__global__ void __launch_bounds__(256)
gemm_gather_kernel(const float* __restrict__ seq,
                   const int*   __restrict__ mraw,
                   const int*   __restrict__ craw,
                   const float* __restrict__ W,
                   const float* __restrict__ bias)
{
    __shared__ float As[2][BK][132];      // padded; A stored k-major (rows contiguous)
    __shared__ float Bs[2][BK][BN];
    __shared__ unsigned rowoff[BM];
    __shared__ int nzm;

    const int tid  = threadIdx.x;
    const int row0 = blockIdx.y * BM;
    const int col0 = blockIdx.x * BN;

    // --- inline dtype detection for masked_positions (per-CTA, ~0 cost) ---
    // int64 LE nonneg < 2^31 => odd 32-bit words all zero. 256 samples, fp~0.
    if (tid == 0) nzm = 0;
    __syncthreads();
    if (mraw[2 * tid + 1] != 0) atomicOr(&nzm, 1);     // words [1,511] < M_=2432 safe
    // CTA 0 also detects candidate dtype and publishes for the logits kernel.
    if (blockIdx.x == 0 && blockIdx.y == 0) {
        __shared__ int nzc;
        if (tid == 0) nzc = 0;
        __syncthreads();
        if (craw[2 * tid + 1] != 0) atomicOr(&nzc, 1); // words < 4096 <= M_*K_ safe
        __syncthreads();
        if (tid == 0) g_c64 = (nzc == 0);
    }
    __syncthreads();
    const int m64 = (nzm == 0);

    if (tid < BM) {
        int m   = row0 + tid;
        int b   = m / P_;
        int pos = m64 ? mraw[2 * m] : mraw[m];
        rowoff[tid] = (unsigned)(b * S_ + pos) * H_;
    }
    __syncthreads();

    // Loader indices
    const int arow = tid >> 2;            // 0..63
    const int acol = (tid & 3) * 4;       // 0,4,8,12
    const int bkr  = tid >> 5;            // 0..7 (k-row; +8 for second half)
    const int bcol = (tid & 31) * 4;      // 0..124

    const int ty = tid >> 4;              // 0..15 -> rows ty*8..+7
    const int tx = tid & 15;              // 0..15 -> cols tx*8..+7

    unsigned long long acc[4][8];         // [row-pair][col], f32x2 over rows
#pragma unroll
    for (int i = 0; i < 4; i++)
#pragma unroll
        for (int j = 0; j < 8; j++) acc[i][j] = 0ULL;

    // Prologue: k-tile 0 -> buffer 0
    {
        float4 a0 = *(const float4*)(seq + rowoff[arow]      + acol);
        float4 a1 = *(const float4*)(seq + rowoff[arow + 64] + acol);
        As[0][acol + 0][arow] = a0.x;  As[0][acol + 1][arow] = a0.y;
        As[0][acol + 2][arow] = a0.z;  As[0][acol + 3][arow] = a0.w;
        As[0][acol + 0][arow + 64] = a1.x;  As[0][acol + 1][arow + 64] = a1.y;
        As[0][acol + 2][arow + 64] = a1.z;  As[0][acol + 3][arow + 64] = a1.w;
        *(float4*)&Bs[0][bkr    ][bcol] = *(const float4*)(W + (size_t)bkr       * E_ + col0 + bcol);
        *(float4*)&Bs[0][bkr + 8][bcol] = *(const float4*)(W + (size_t)(bkr + 8) * E_ + col0 + bcol);
    }
    __syncthreads();

    const int NIT = H_ / BK;              // 48
    for (int it = 0; it < NIT; ++it) {
        const int p = it & 1;

        float4 pa0, pa1, pb0, pb1;
        if (it < NIT - 1) {
            const int k0 = (it + 1) * BK;
            pa0 = *(const float4*)(seq + rowoff[arow]      + k0 + acol);
            pa1 = *(const float4*)(seq + rowoff[arow + 64] + k0 + acol);
            pb0 = *(const float4*)(W + (size_t)(k0 + bkr)     * E_ + col0 + bcol);
            pb1 = *(const float4*)(W + (size_t)(k0 + bkr + 8) * E_ + col0 + bcol);
        }

#pragma unroll
        for (int k = 0; k < BK; ++k) {
            // A row-pairs: 4 x LDS.64 (8B-aligned: 528*k + 32*ty)
            const unsigned long long* ap =
                (const unsigned long long*)&As[p][k][ty * 8];
            unsigned long long a0 = ap[0], a1 = ap[1], a2 = ap[2], a3 = ap[3];
            // B cols: 2 x LDS.128
            float4 b03 = *(const float4*)&Bs[p][k][tx * 8];
            float4 b47 = *(const float4*)&Bs[p][k][tx * 8 + 4];
            const float bv[8] = { b03.x, b03.y, b03.z, b03.w,
                                  b47.x, b47.y, b47.z, b47.w };
#pragma unroll
            for (int c = 0; c < 8; ++c) {
                unsigned long long bd;
                asm("mov.b64 %0, {%1, %1};" : "=l"(bd) : "f"(bv[c]));
                asm("fma.rn.f32x2 %0, %1, %2, %0;" : "+l"(acc[0][c]) : "l"(a0), "l"(bd));
                asm("fma.rn.f32x2 %0, %1, %2, %0;" : "+l"(acc[1][c]) : "l"(a1), "l"(bd));
                asm("fma.rn.f32x2 %0, %1, %2, %0;" : "+l"(acc[2][c]) : "l"(a2), "l"(bd));
                asm("fma.rn.f32x2 %0, %1, %2, %0;" : "+l"(acc[3][c]) : "l"(a3), "l"(bd));
            }
        }

        if (it < NIT - 1) {
            const int q = 1 - p;
            As[q][acol + 0][arow] = pa0.x;  As[q][acol + 1][arow] = pa0.y;
            As[q][acol + 2][arow] = pa0.z;  As[q][acol + 3][arow] = pa0.w;
            As[q][acol + 0][arow + 64] = pa1.x;  As[q][acol + 1][arow + 64] = pa1.y;
            As[q][acol + 2][arow + 64] = pa1.z;  As[q][acol + 3][arow + 64] = pa1.w;
            *(float4*)&Bs[q][bkr    ][bcol] = pb0;
            *(float4*)&Bs[q][bkr + 8][bcol] = pb1;
        }
        __syncthreads();
    }

    // Epilogue: + bias, write to scratch (two rows per row-pair)
    float bvz[8];
#pragma unroll
    for (int j = 0; j < 8; j++) bvz[j] = bias[col0 + tx * 8 + j];

#pragma unroll
    for (int rp = 0; rp < 4; rp++) {
        float lo[8], hi[8];
#pragma unroll
        for (int c = 0; c < 8; c++) {
            unsigned l32, h32;
            asm("mov.b64 {%0, %1}, %2;" : "=r"(l32), "=r"(h32) : "l"(acc[rp][c]));
            lo[c] = __uint_as_float(l32) + bvz[c];
            hi[c] = __uint_as_float(h32) + bvz[c];
        }
        int m0 = row0 + ty * 8 + rp * 2;
        float* d0 = g_lm + (size_t)m0 * E_ + col0 + tx * 8;
        float* d1 = d0 + E_;
        *(float4*)(d0)     = make_float4(lo[0], lo[1], lo[2], lo[3]);
        *(float4*)(d0 + 4) = make_float4(lo[4], lo[5], lo[6], lo[7]);
        *(float4*)(d1)     = make_float4(hi[0], hi[1], hi[2], hi[3]);
        *(float4*)(d1 + 4) = make_float4(hi[4], hi[5], hi[6], hi[7]);
    }
}

// ---------------------------------------------------------------------------
// Kernel 2: per-(b,p) LayerNorm (fused) + 64 candidate-embedding dot products.
// One block per row (2432 blocks), 256 threads = 8 warps x 8 candidates.
// Candidates processed 4-wide for memory-level parallelism.
// ---------------------------------------------------------------------------
__global__ void __launch_bounds__(256)
logits_kernel(const int*   __restrict__ craw,
              const float* __restrict__ emb,
              const float* __restrict__ gamma,
              const float* __restrict__ beta,
              float* __restrict__ out)
{
    __shared__ __align__(16) float lm_s[E_];
    __shared__ float red[16];
    __shared__ float mu_s, rinv_s;

    const int bp   = blockIdx.x;
    const int tid  = threadIdx.x;
    const int wid  = tid >> 5;
    const int lane = tid & 31;
    const int c64  = g_c64;

    const float* row = g_lm + (size_t)bp * E_;
    float x0 = row[tid];
    float x1 = row[tid + 256];
    float x2 = row[tid + 512];

    float s  = x0 + x1 + x2;
    float sq = x0 * x0 + x1 * x1 + x2 * x2;
#pragma unroll
    for (int o = 16; o; o >>= 1) {
        s  += __shfl_xor_sync(0xffffffffu, s,  o);
        sq += __shfl_xor_sync(0xffffffffu, sq, o);
    }
    if (lane == 0) { red[wid] = s; red[wid + 8] = sq; }
    __syncthreads();
    if (tid == 0) {
        float S = 0.f, SQ = 0.f;
#pragma unroll
        for (int w = 0; w < 8; w++) { S += red[w]; SQ += red[w + 8]; }
        float mu  = S * (1.0f / E_);
        float var = SQ * (1.0f / E_) - mu * mu;
        mu_s   = mu;
        rinv_s = rsqrtf(var + 1e-12f);
    }
    __syncthreads();
    const float mu = mu_s, rinv = rinv_s;

    lm_s[tid]       = (x0 - mu) * rinv * gamma[tid]       + beta[tid];
    lm_s[tid + 256] = (x1 - mu) * rinv * gamma[tid + 256] + beta[tid + 256];
    lm_s[tid + 512] = (x2 - mu) * rinv * gamma[tid + 512] + beta[tid + 512];
    __syncthreads();

    const float4* lp = (const float4*)lm_s;

#pragma unroll
    for (int kk = 0; kk < 2; kk++) {
        int k  = wid * 8 + kk * 4;
        int i0 = bp * K_ + k;
        int c0 = c64 ? craw[2 * i0]     : craw[i0];
        int c1 = c64 ? craw[2 * i0 + 2] : craw[i0 + 1];
        int c2 = c64 ? craw[2 * i0 + 4] : craw[i0 + 2];
        int c3 = c64 ? craw[2 * i0 + 6] : craw[i0 + 3];
        const float4* e0 = (const float4*)(emb + (size_t)c0 * E_);
        const float4* e1 = (const float4*)(emb + (size_t)c1 * E_);
        const float4* e2 = (const float4*)(emb + (size_t)c2 * E_);
        const float4* e3 = (const float4*)(emb + (size_t)c3 * E_);
        float a0 = 0.f, a1 = 0.f, a2 = 0.f, a3 = 0.f;
#pragma unroll
        for (int j = 0; j < 6; j++) {
            float4 l = lp[j * 32 + lane];
            float4 v0 = e0[j * 32 + lane];
            float4 v1 = e1[j * 32 + lane];
            float4 v2 = e2[j * 32 + lane];
            float4 v3 = e3[j * 32 + lane];
            a0 += v0.x * l.x + v0.y * l.y + v0.z * l.z + v0.w * l.w;
            a1 += v1.x * l.x + v1.y * l.y + v1.z * l.z + v1.w * l.w;
            a2 += v2.x * l.x + v2.y * l.y + v2.z * l.z + v2.w * l.w;
            a3 += v3.x * l.x + v3.y * l.y + v3.z * l.z + v3.w * l.w;
        }
#pragma unroll
        for (int o = 16; o; o >>= 1) {
            a0 += __shfl_xor_sync(0xffffffffu, a0, o);
            a1 += __shfl_xor_sync(0xffffffffu, a1, o);
            a2 += __shfl_xor_sync(0xffffffffu, a2, o);
            a3 += __shfl_xor_sync(0xffffffffu, a3, o);
        }
        if (lane == 0) {
            out[i0]     = a0;
            out[i0 + 1] = a1;
            out[i0 + 2] = a2;
            out[i0 + 3] = a3;
        }
    }
}

// ---------------------------------------------------------------------------
extern "C" void kernel_launch(void* const* d_in, const int* in_sizes, int n_in,
                              void* d_out, int out_size)
{
    const float* seq   = (const float*)d_in[0];
    const int*   mraw  = (const int*)d_in[1];
    const int*   craw  = (const int*)d_in[2];
    const float* emb   = (const float*)d_in[3];
    const float* W     = (const float*)d_in[4];
    const float* bias  = (const float*)d_in[5];
    const float* gamma = (const float*)d_in[6];
    const float* beta  = (const float*)d_in[7];
    float*       out   = (float*)d_out;

    dim3 g1(E_ / BN, M_ / BM);   // 6 x 19 = 114 CTAs -> one wave
    gemm_gather_kernel<<<g1, 256>>>(seq, mraw, craw, W, bias);
    logits_kernel<<<M_, 256>>>(craw, emb, gamma, beta, out);
}

// round 5
// speedup vs baseline: 1.0908x; 1.0908x over previous
#include <cuda_runtime.h>
#include <cstdint>

// Problem constants (fixed shapes from reference)
#define B_  32
#define S_  512
#define H_  768
#define P_  76
#define K_  64
#define E_  768
#define M_  (B_ * P_)     // 2432 rows

#define BM 64
#define BN 96
#define BK 16

// Scratch
__device__ float g_lm[M_ * E_];          // 7.1 MB pre-LN dense output
__device__ int   g_c64;                  // candidate_sets stored as int64? (set by GEMM CTA 0)

// ---------------------------------------------------------------------------
// Kernel 1: gathered-A SGEMM via packed fp32x2 FMA (FFMA2, 2x FFMA rate).
// 64x96 tile, grid 8 x 38 = 304 CTAs -> ~2 CTAs/SM concurrent, ~1.03 waves.
// 256 threads, 4-row x 6-col microtile (3 f32x2 col-pairs per row).
// Inner loop identical in structure to the proven R3 kernel (A scalar dup,
// B natural f32x2 pairs).  Double-buffered smem + register prefetch.
// ---------------------------------------------------------------------------
__global__ void __launch_bounds__(256)
gemm_gather_kernel(const float* __restrict__ seq,
                   const int*   __restrict__ mraw,
                   const int*   __restrict__ craw,
                   const float* __restrict__ W,
                   const float* __restrict__ bias)
{
    __shared__ float As[2][BK][BM + 4];   // padded; A stored k-major
    __shared__ float Bs[2][BK][BN];
    __shared__ unsigned rowoff[BM];
    __shared__ int nzm;

    const int tid  = threadIdx.x;
    const int row0 = blockIdx.y * BM;
    const int col0 = blockIdx.x * BN;

    // --- inline index-dtype detection (int64 LE nonneg < 2^31 => odd words 0)
    if (tid == 0) nzm = 0;
    __syncthreads();
    if (mraw[2 * tid + 1] != 0) atomicOr(&nzm, 1);     // 512 words <= M_ safe
    if (blockIdx.x == 0 && blockIdx.y == 0) {
        __shared__ int nzc;
        if (tid == 0) nzc = 0;
        __syncthreads();
        if (craw[2 * tid + 1] != 0) atomicOr(&nzc, 1); // 512 words <= M_*K_ safe
        __syncthreads();
        if (tid == 0) g_c64 = (nzc == 0);
    }
    __syncthreads();
    const int m64 = (nzm == 0);

    if (tid < BM) {
        int m   = row0 + tid;
        int b   = m / P_;
        int pos = m64 ? mraw[2 * m] : mraw[m];
        rowoff[tid] = (unsigned)(b * S_ + pos) * H_;
    }
    __syncthreads();

    // Loader indices
    const int arow = tid >> 2;            // 0..63
    const int acol = (tid & 3) * 4;       // 0,4,8,12
    int bkr[3], bc2[3];                   // B: 3 float2 per thread (16x96 tile)
#pragma unroll
    for (int i = 0; i < 3; i++) {
        int l  = tid + i * 256;
        bkr[i] = l / 48;                  // k-row 0..15
        bc2[i] = (l % 48) * 2;            // col 0..94 (even)
    }

    const int ty = tid >> 4;              // 0..15 -> rows ty*4..+3
    const int tx = tid & 15;              // 0..15 -> cols tx*6..+5

    unsigned long long acc[4][3];         // [row][col-pair], f32x2 over cols
#pragma unroll
    for (int i = 0; i < 4; i++)
#pragma unroll
        for (int j = 0; j < 3; j++) acc[i][j] = 0ULL;

    // Prologue: k-tile 0 -> buffer 0
    {
        float4 a0 = *(const float4*)(seq + rowoff[arow] + acol);
        As[0][acol + 0][arow] = a0.x;  As[0][acol + 1][arow] = a0.y;
        As[0][acol + 2][arow] = a0.z;  As[0][acol + 3][arow] = a0.w;
#pragma unroll
        for (int i = 0; i < 3; i++)
            *(float2*)&Bs[0][bkr[i]][bc2[i]] =
                *(const float2*)(W + (size_t)bkr[i] * E_ + col0 + bc2[i]);
    }
    __syncthreads();

    const int NIT = H_ / BK;              // 48
    for (int it = 0; it < NIT; ++it) {
        const int p = it & 1;

        float4 pa;
        float2 pb[3];
        if (it < NIT - 1) {
            const int k0 = (it + 1) * BK;
            pa = *(const float4*)(seq + rowoff[arow] + k0 + acol);
#pragma unroll
            for (int i = 0; i < 3; i++)
                pb[i] = *(const float2*)(W + (size_t)(k0 + bkr[i]) * E_
                                           + col0 + bc2[i]);
        }

#pragma unroll
        for (int k = 0; k < BK; ++k) {
            unsigned long long bv0 = *(const unsigned long long*)&Bs[p][k][tx * 6 + 0];
            unsigned long long bv1 = *(const unsigned long long*)&Bs[p][k][tx * 6 + 2];
            unsigned long long bv2 = *(const unsigned long long*)&Bs[p][k][tx * 6 + 4];
#pragma unroll
            for (int i = 0; i < 4; ++i) {
                unsigned au = __float_as_uint(As[p][k][ty * 4 + i]);
                unsigned long long ad;
                asm("mov.b64 %0, {%1, %1};" : "=l"(ad) : "r"(au));
                asm("fma.rn.f32x2 %0, %1, %2, %0;" : "+l"(acc[i][0]) : "l"(ad), "l"(bv0));
                asm("fma.rn.f32x2 %0, %1, %2, %0;" : "+l"(acc[i][1]) : "l"(ad), "l"(bv1));
                asm("fma.rn.f32x2 %0, %1, %2, %0;" : "+l"(acc[i][2]) : "l"(ad), "l"(bv2));
            }
        }

        if (it < NIT - 1) {
            const int q = 1 - p;
            As[q][acol + 0][arow] = pa.x;  As[q][acol + 1][arow] = pa.y;
            As[q][acol + 2][arow] = pa.z;  As[q][acol + 3][arow] = pa.w;
#pragma unroll
            for (int i = 0; i < 3; i++)
                *(float2*)&Bs[q][bkr[i]][bc2[i]] = pb[i];
        }
        __syncthreads();
    }

    // Epilogue: + bias, write to scratch
    float2 bb[3];
#pragma unroll
    for (int j = 0; j < 3; j++)
        bb[j] = *(const float2*)(bias + col0 + tx * 6 + 2 * j);

#pragma unroll
    for (int i = 0; i < 4; i++) {
        int m = row0 + ty * 4 + i;
        float* dst = g_lm + (size_t)m * E_ + col0 + tx * 6;
#pragma unroll
        for (int j = 0; j < 3; j++) {
            unsigned lo, hi;
            asm("mov.b64 {%0, %1}, %2;" : "=r"(lo), "=r"(hi) : "l"(acc[i][j]));
            float2 v;
            v.x = __uint_as_float(lo) + bb[j].x;
            v.y = __uint_as_float(hi) + bb[j].y;
            *(float2*)(dst + 2 * j) = v;
        }
    }
}

// ---------------------------------------------------------------------------
// Kernel 2: per-(b,p) LayerNorm (fused) + 64 candidate-embedding dot products.
// One block per row (2432 blocks), 256 threads = 8 warps x 8 candidates,
// processed in pairs.  launch_bounds(256,5) -> <=51 regs, ~5 CTAs/SM.
// ---------------------------------------------------------------------------
__global__ void __launch_bounds__(256, 5)
logits_kernel(const int*   __restrict__ craw,
              const float* __restrict__ emb,
              const float* __restrict__ gamma,
              const float* __restrict__ beta,
              float* __restrict__ out)
{
    __shared__ __align__(16) float lm_s[E_];
    __shared__ float red[16];
    __shared__ float mu_s, rinv_s;

    const int bp   = blockIdx.x;
    const int tid  = threadIdx.x;
    const int wid  = tid >> 5;
    const int lane = tid & 31;
    const int c64  = g_c64;

    const float* row = g_lm + (size_t)bp * E_;
    float x0 = row[tid];
    float x1 = row[tid + 256];
    float x2 = row[tid + 512];

    float s  = x0 + x1 + x2;
    float sq = x0 * x0 + x1 * x1 + x2 * x2;
#pragma unroll
    for (int o = 16; o; o >>= 1) {
        s  += __shfl_xor_sync(0xffffffffu, s,  o);
        sq += __shfl_xor_sync(0xffffffffu, sq, o);
    }
    if (lane == 0) { red[wid] = s; red[wid + 8] = sq; }
    __syncthreads();
    if (tid == 0) {
        float S = 0.f, SQ = 0.f;
#pragma unroll
        for (int w = 0; w < 8; w++) { S += red[w]; SQ += red[w + 8]; }
        float mu  = S * (1.0f / E_);
        float var = SQ * (1.0f / E_) - mu * mu;
        mu_s   = mu;
        rinv_s = rsqrtf(var + 1e-12f);
    }
    __syncthreads();
    const float mu = mu_s, rinv = rinv_s;

    lm_s[tid]       = (x0 - mu) * rinv * gamma[tid]       + beta[tid];
    lm_s[tid + 256] = (x1 - mu) * rinv * gamma[tid + 256] + beta[tid + 256];
    lm_s[tid + 512] = (x2 - mu) * rinv * gamma[tid + 512] + beta[tid + 512];
    __syncthreads();

    const float4* lp = (const float4*)lm_s;

#pragma unroll
    for (int kk = 0; kk < 4; kk++) {
        int k  = wid * 8 + kk * 2;
        int i0 = bp * K_ + k;
        int c0 = c64 ? craw[2 * i0]     : craw[i0];
        int c1 = c64 ? craw[2 * i0 + 2] : craw[i0 + 1];
        const float4* e0 = (const float4*)(emb + (size_t)c0 * E_);
        const float4* e1 = (const float4*)(emb + (size_t)c1 * E_);
        float a0 = 0.f, a1 = 0.f;
#pragma unroll
        for (int j = 0; j < 6; j++) {
            float4 l  = lp[j * 32 + lane];
            float4 v0 = e0[j * 32 + lane];
            float4 v1 = e1[j * 32 + lane];
            a0 += v0.x * l.x + v0.y * l.y + v0.z * l.z + v0.w * l.w;
            a1 += v1.x * l.x + v1.y * l.y + v1.z * l.z + v1.w * l.w;
        }
#pragma unroll
        for (int o = 16; o; o >>= 1) {
            a0 += __shfl_xor_sync(0xffffffffu, a0, o);
            a1 += __shfl_xor_sync(0xffffffffu, a1, o);
        }
        if (lane == 0) {
            out[i0]     = a0;
            out[i0 + 1] = a1;
        }
    }
}

// ---------------------------------------------------------------------------
extern "C" void kernel_launch(void* const* d_in, const int* in_sizes, int n_in,
                              void* d_out, int out_size)
{
    const float* seq   = (const float*)d_in[0];
    const int*   mraw  = (const int*)d_in[1];
    const int*   craw  = (const int*)d_in[2];
    const float* emb   = (const float*)d_in[3];
    const float* W     = (const float*)d_in[4];
    const float* bias  = (const float*)d_in[5];
    const float* gamma = (const float*)d_in[6];
    const float* beta  = (const float*)d_in[7];
    float*       out   = (float*)d_out;

    dim3 g1(E_ / BN, M_ / BM);   // 8 x 38 = 304 CTAs
    gemm_gather_kernel<<<g1, 256>>>(seq, mraw, craw, W, bias);
    logits_kernel<<<M_, 256>>>(craw, emb, gamma, beta, out);
}

// round 7
// speedup vs baseline: 1.6248x; 1.4896x over previous
#include <cuda_runtime.h>
#include <cuda_bf16.h>
#include <cstdint>

// Problem constants (fixed shapes from reference)
#define B_  32
#define S_  512
#define H_  768
#define P_  76
#define K_  64
#define E_  768
#define M_  (B_ * P_)     // 2432

// ---------------- device scratch (no allocs allowed) ----------------
__device__ __align__(16) float          g_lm[M_ * E_];    // pre-LN dense out
__device__ __align__(16) __nv_bfloat16  g_ahi[M_ * H_];   // gathered A hi
__device__ __align__(16) __nv_bfloat16  g_alo[M_ * H_];   // gathered A lo
__device__ __align__(16) __nv_bfloat16  g_whi[H_ * E_];   // W hi (row-major, = mma B)
__device__ __align__(16) __nv_bfloat16  g_wlo[H_ * E_];   // W lo
__device__ int g_c64;                                     // cand idx int64?

// ---------------- helpers ----------------
__device__ __forceinline__ uint32_t smem_u32(const void* p) {
    uint32_t a;
    asm("{ .reg .u64 t; cvta.to.shared.u64 t, %1; cvt.u32.u64 %0, t; }"
        : "=r"(a) : "l"(p));
    return a;
}
__device__ __forceinline__ void cp16(uint32_t s, const void* g) {
    asm volatile("cp.async.cg.shared.global [%0], [%1], 16;" :: "r"(s), "l"(g));
}
__device__ __forceinline__ void ldm_x4(uint32_t* r, uint32_t addr) {
    asm volatile("ldmatrix.sync.aligned.m8n8.x4.shared.b16 {%0,%1,%2,%3}, [%4];"
                 : "=r"(r[0]), "=r"(r[1]), "=r"(r[2]), "=r"(r[3]) : "r"(addr));
}
__device__ __forceinline__ void ldm_x4_t(uint32_t* r, uint32_t addr) {
    asm volatile("ldmatrix.sync.aligned.m8n8.x4.trans.shared.b16 {%0,%1,%2,%3}, [%4];"
                 : "=r"(r[0]), "=r"(r[1]), "=r"(r[2]), "=r"(r[3]) : "r"(addr));
}
__device__ __forceinline__ void mma_bf16(float* d, const uint32_t* a,
                                         uint32_t b0, uint32_t b1) {
    asm volatile(
        "mma.sync.aligned.m16n8k16.row.col.f32.bf16.bf16.f32 "
        "{%0,%1,%2,%3}, {%4,%5,%6,%7}, {%8,%9}, {%0,%1,%2,%3};"
        : "+f"(d[0]), "+f"(d[1]), "+f"(d[2]), "+f"(d[3])
        : "r"(a[0]), "r"(a[1]), "r"(a[2]), "r"(a[3]), "r"(b0), "r"(b1));
}

// ---------------------------------------------------------------------------
// Prep: blocks [0,2304): split W -> bf16 hi/lo elementwise (blk 0: cand detect)
//       blocks [2304,4736): gather seq rows via masked_positions -> bf16 hi/lo
// Index dtype detection: int64 LE nonneg < 2^31 => odd 32-bit words all zero.
// ---------------------------------------------------------------------------
__global__ void __launch_bounds__(256)
prep_kernel(const float* __restrict__ seq, const int* __restrict__ mraw,
            const int* __restrict__ craw, const float* __restrict__ W)
{
    const int blk = blockIdx.x;
    const int tid = threadIdx.x;

    if (blk < 2304) {
        int idx = blk * 256 + tid;            // < 589824 = 768*768
        float v = W[idx];
        __nv_bfloat16 hi = __float2bfloat16(v);
        __nv_bfloat16 lo = __float2bfloat16(v - __bfloat162float(hi));
        g_whi[idx] = hi;
        g_wlo[idx] = lo;
        if (blk == 0) {
            __shared__ int nzc;
            if (tid == 0) nzc = 0;
            __syncthreads();
            if (craw[2 * tid + 1] != 0) atomicOr(&nzc, 1);   // 512 words <= M_*K_
            __syncthreads();
            if (tid == 0) g_c64 = (nzc == 0);
        }
    } else {
        const int m = blk - 2304;             // 0..2431
        __shared__ int nzm;
        if (tid == 0) nzm = 0;
        __syncthreads();
        if (mraw[2 * tid + 1] != 0) atomicOr(&nzm, 1);       // 512 words <= M_
        __syncthreads();
        const int pos = (nzm == 0) ? mraw[2 * m] : mraw[m];
        const int b = m / P_;
        const float* src = seq + (size_t)(b * S_ + pos) * H_;
#pragma unroll
        for (int j = 0; j < 3; j++) {
            int i = tid + j * 256;
            float v = src[i];
            __nv_bfloat16 hi = __float2bfloat16(v);
            __nv_bfloat16 lo = __float2bfloat16(v - __bfloat162float(hi));
            g_ahi[(size_t)m * H_ + i] = hi;
            g_alo[(size_t)m * H_ + i] = lo;
        }
    }
}

// ---------------------------------------------------------------------------
// GEMM: bf16 mma.sync m16n8k16 with 3-term hi/lo split (fp32-accurate).
// 128x128 tile/CTA, grid 6 x 19 = 114 CTAs -> one wave.
// 8 warps (2m x 4n), warp tile 64x32. K chunks of 32, cp.async double buffer.
// smem strides padded (A:40, B:136 bf16) for conflict-free ldmatrix.
// ---------------------------------------------------------------------------
#define A_STR 40
#define B_STR 136
#define OFF_AHI(buf) ((buf) * 10240)                  // 128*40*2
#define OFF_ALO(buf) (20480 + (buf) * 10240)
#define OFF_BHI(buf) (40960 + (buf) * 8704)           // 32*136*2
#define OFF_BLO(buf) (58368 + (buf) * 8704)
#define SMEM_BYTES  75776

__global__ void __launch_bounds__(256)
gemm_mma_kernel(const float* __restrict__ bias)
{
    extern __shared__ __align__(16) char smem[];
    const uint32_t sb = smem_u32(smem);
    const int tid  = threadIdx.x;
    const int wid  = tid >> 5;
    const int lane = tid & 31;
    const int row0 = blockIdx.y * 128;
    const int col0 = blockIdx.x * 128;
    const int wm   = (wid >> 2) * 64;     // warp m offset
    const int wn   = (wid & 3) * 32;      // warp n offset

    // per-thread load slots
    const int ar = tid >> 2, ac = (tid & 3) * 8;           // A: row, col(bf16)
    const int br = tid >> 4, bc = (tid & 15) * 8;          // B: krow, col

    float acc[4][4][4];
#pragma unroll
    for (int i = 0; i < 4; i++)
#pragma unroll
        for (int j = 0; j < 4; j++)
#pragma unroll
            for (int q = 0; q < 4; q++) acc[i][j][q] = 0.f;

    auto load_chunk = [&](int c, int buf) {
        const int k0 = c * 32;
        const __nv_bfloat16* pa = g_ahi + (size_t)(row0 + ar) * H_ + k0 + ac;
        const __nv_bfloat16* pl = g_alo + (size_t)(row0 + ar) * H_ + k0 + ac;
        cp16(sb + OFF_AHI(buf) + (ar * A_STR + ac) * 2, pa);
        cp16(sb + OFF_AHI(buf) + ((ar + 64) * A_STR + ac) * 2, pa + (size_t)64 * H_);
        cp16(sb + OFF_ALO(buf) + (ar * A_STR + ac) * 2, pl);
        cp16(sb + OFF_ALO(buf) + ((ar + 64) * A_STR + ac) * 2, pl + (size_t)64 * H_);
        const __nv_bfloat16* pb = g_whi + (size_t)(k0 + br) * E_ + col0 + bc;
        const __nv_bfloat16* pw = g_wlo + (size_t)(k0 + br) * E_ + col0 + bc;
        cp16(sb + OFF_BHI(buf) + (br * B_STR + bc) * 2, pb);
        cp16(sb + OFF_BHI(buf) + ((br + 16) * B_STR + bc) * 2, pb + (size_t)16 * E_);
        cp16(sb + OFF_BLO(buf) + (br * B_STR + bc) * 2, pw);
        cp16(sb + OFF_BLO(buf) + ((br + 16) * B_STR + bc) * 2, pw + (size_t)16 * E_);
    };

    load_chunk(0, 0);
    asm volatile("cp.async.commit_group;" ::: "memory");

    const int l15 = lane & 15, lh = lane >> 4;

    for (int c = 0; c < 24; ++c) {
        const int buf = c & 1;
        if (c + 1 < 24) {
            load_chunk(c + 1, 1 - buf);
            asm volatile("cp.async.commit_group;" ::: "memory");
            asm volatile("cp.async.wait_group 1;" ::: "memory");
        } else {
            asm volatile("cp.async.wait_group 0;" ::: "memory");
        }
        __syncthreads();

#pragma unroll
        for (int ks = 0; ks < 2; ++ks) {
            // B fragments: 2 n16-groups, hi and lo
            uint32_t bh[2][4], bl[2][4];
#pragma unroll
            for (int g = 0; g < 2; ++g) {
                uint32_t ba = (uint32_t)((ks * 16 + l15) * B_STR
                                         + wn + g * 16 + lh * 8) * 2;
                ldm_x4_t(bh[g], sb + OFF_BHI(buf) + ba);
                ldm_x4_t(bl[g], sb + OFF_BLO(buf) + ba);
            }
#pragma unroll
            for (int mf = 0; mf < 4; ++mf) {
                uint32_t aa = (uint32_t)((wm + mf * 16 + l15) * A_STR
                                         + ks * 16 + lh * 8) * 2;
                uint32_t ah[4], al[4];
                ldm_x4(ah, sb + OFF_AHI(buf) + aa);
                ldm_x4(al, sb + OFF_ALO(buf) + aa);
#pragma unroll
                for (int g = 0; g < 2; ++g) {
#pragma unroll
                    for (int s = 0; s < 2; ++s) {
                        float* d = acc[mf][g * 2 + s];
                        mma_bf16(d, ah, bh[g][s * 2], bh[g][s * 2 + 1]);
                        mma_bf16(d, ah, bl[g][s * 2], bl[g][s * 2 + 1]);
                        mma_bf16(d, al, bh[g][s * 2], bh[g][s * 2 + 1]);
                    }
                }
            }
        }
        __syncthreads();
    }

    // Epilogue: + bias, fp32 store
    const int lr = lane >> 2, lc2 = (lane & 3) * 2;
#pragma unroll
    for (int nf = 0; nf < 4; ++nf) {
        const int col = col0 + wn + nf * 8 + lc2;
        const float2 bb = *(const float2*)(bias + col);
#pragma unroll
        for (int mf = 0; mf < 4; ++mf) {
            const int r0 = row0 + wm + mf * 16 + lr;
            float2 v0, v1;
            v0.x = acc[mf][nf][0] + bb.x;  v0.y = acc[mf][nf][1] + bb.y;
            v1.x = acc[mf][nf][2] + bb.x;  v1.y = acc[mf][nf][3] + bb.y;
            *(float2*)(g_lm + (size_t)r0 * E_ + col)       = v0;
            *(float2*)(g_lm + (size_t)(r0 + 8) * E_ + col) = v1;
        }
    }
}

// ---------------------------------------------------------------------------
// Logits: per-(b,p) LayerNorm (fused) + 64 candidate dots (proven R3 version).
// ---------------------------------------------------------------------------
__global__ void __launch_bounds__(256)
logits_kernel(const int*   __restrict__ craw,
              const float* __restrict__ emb,
              const float* __restrict__ gamma,
              const float* __restrict__ beta,
              float* __restrict__ out)
{
    __shared__ __align__(16) float lm_s[E_];
    __shared__ float red[16];
    __shared__ float mu_s, rinv_s;

    const int bp   = blockIdx.x;
    const int tid  = threadIdx.x;
    const int wid  = tid >> 5;
    const int lane = tid & 31;
    const int c64  = g_c64;

    const float* row = g_lm + (size_t)bp * E_;
    float x0 = row[tid];
    float x1 = row[tid + 256];
    float x2 = row[tid + 512];

    float s  = x0 + x1 + x2;
    float sq = x0 * x0 + x1 * x1 + x2 * x2;
#pragma unroll
    for (int o = 16; o; o >>= 1) {
        s  += __shfl_xor_sync(0xffffffffu, s,  o);
        sq += __shfl_xor_sync(0xffffffffu, sq, o);
    }
    if (lane == 0) { red[wid] = s; red[wid + 8] = sq; }
    __syncthreads();
    if (tid == 0) {
        float S = 0.f, SQ = 0.f;
#pragma unroll
        for (int w = 0; w < 8; w++) { S += red[w]; SQ += red[w + 8]; }
        float mu  = S * (1.0f / E_);
        float var = SQ * (1.0f / E_) - mu * mu;
        mu_s   = mu;
        rinv_s = rsqrtf(var + 1e-12f);
    }
    __syncthreads();
    const float mu = mu_s, rinv = rinv_s;

    lm_s[tid]       = (x0 - mu) * rinv * gamma[tid]       + beta[tid];
    lm_s[tid + 256] = (x1 - mu) * rinv * gamma[tid + 256] + beta[tid + 256];
    lm_s[tid + 512] = (x2 - mu) * rinv * gamma[tid + 512] + beta[tid + 512];
    __syncthreads();

    const float4* lp = (const float4*)lm_s;

#pragma unroll
    for (int kk = 0; kk < 4; kk++) {
        int k  = wid * 8 + kk * 2;
        int i0 = bp * K_ + k;
        int c0 = c64 ? craw[2 * i0]     : craw[i0];
        int c1 = c64 ? craw[2 * i0 + 2] : craw[i0 + 1];
        const float4* e0 = (const float4*)(emb + (size_t)c0 * E_);
        const float4* e1 = (const float4*)(emb + (size_t)c1 * E_);
        float a0 = 0.f, a1 = 0.f;
#pragma unroll
        for (int j = 0; j < 6; j++) {
            float4 l  = lp[j * 32 + lane];
            float4 v0 = e0[j * 32 + lane];
            float4 v1 = e1[j * 32 + lane];
            a0 += v0.x * l.x + v0.y * l.y + v0.z * l.z + v0.w * l.w;
            a1 += v1.x * l.x + v1.y * l.y + v1.z * l.z + v1.w * l.w;
        }
#pragma unroll
        for (int o = 16; o; o >>= 1) {
            a0 += __shfl_xor_sync(0xffffffffu, a0, o);
            a1 += __shfl_xor_sync(0xffffffffu, a1, o);
        }
        if (lane == 0) {
            out[i0]     = a0;
            out[i0 + 1] = a1;
        }
    }
}

// ---------------------------------------------------------------------------
extern "C" void kernel_launch(void* const* d_in, const int* in_sizes, int n_in,
                              void* d_out, int out_size)
{
    const float* seq   = (const float*)d_in[0];
    const int*   mraw  = (const int*)d_in[1];
    const int*   craw  = (const int*)d_in[2];
    const float* emb   = (const float*)d_in[3];
    const float* W     = (const float*)d_in[4];
    const float* bias  = (const float*)d_in[5];
    const float* gamma = (const float*)d_in[6];
    const float* beta  = (const float*)d_in[7];
    float*       out   = (float*)d_out;

    cudaFuncSetAttribute(gemm_mma_kernel,
                         cudaFuncAttributeMaxDynamicSharedMemorySize, SMEM_BYTES);

    prep_kernel<<<2304 + M_, 256>>>(seq, mraw, craw, W);
    dim3 g1(E_ / 128, M_ / 128);   // 6 x 19 = 114 CTAs
    gemm_mma_kernel<<<g1, 256, SMEM_BYTES>>>(bias);
    logits_kernel<<<M_, 256>>>(craw, emb, gamma, beta, out);
}

// round 8
// speedup vs baseline: 1.7442x; 1.0735x over previous
#include <cuda_runtime.h>
#include <cuda_bf16.h>
#include <cstdint>

// Problem constants (fixed shapes from reference)
#define B_  32
#define S_  512
#define H_  768
#define P_  76
#define K_  64
#define E_  768
#define M_  (B_ * P_)     // 2432

// ---------------- device scratch (no allocs allowed) ----------------
__device__ __align__(16) float          g_lm[M_ * E_];    // pre-LN dense out
__device__ __align__(16) __nv_bfloat16  g_ahi[M_ * H_];   // gathered A hi
__device__ __align__(16) __nv_bfloat16  g_alo[M_ * H_];   // gathered A lo
__device__ __align__(16) __nv_bfloat16  g_whi[H_ * E_];   // W hi (row-major = mma B)
__device__ __align__(16) __nv_bfloat16  g_wlo[H_ * E_];   // W lo
__device__ int g_c64;                                     // cand idx int64?

// ---------------- helpers ----------------
__device__ __forceinline__ uint32_t smem_u32(const void* p) {
    uint32_t a;
    asm("{ .reg .u64 t; cvta.to.shared.u64 t, %1; cvt.u32.u64 %0, t; }"
        : "=r"(a) : "l"(p));
    return a;
}
__device__ __forceinline__ void cp16(uint32_t s, const void* g) {
    asm volatile("cp.async.cg.shared.global [%0], [%1], 16;" :: "r"(s), "l"(g));
}
__device__ __forceinline__ void ldm_x4(uint32_t* r, uint32_t addr) {
    asm volatile("ldmatrix.sync.aligned.m8n8.x4.shared.b16 {%0,%1,%2,%3}, [%4];"
                 : "=r"(r[0]), "=r"(r[1]), "=r"(r[2]), "=r"(r[3]) : "r"(addr));
}
__device__ __forceinline__ void ldm_x4_t(uint32_t* r, uint32_t addr) {
    asm volatile("ldmatrix.sync.aligned.m8n8.x4.trans.shared.b16 {%0,%1,%2,%3}, [%4];"
                 : "=r"(r[0]), "=r"(r[1]), "=r"(r[2]), "=r"(r[3]) : "r"(addr));
}
__device__ __forceinline__ void mma_bf16(float* d, const uint32_t* a,
                                         uint32_t b0, uint32_t b1) {
    asm volatile(
        "mma.sync.aligned.m16n8k16.row.col.f32.bf16.bf16.f32 "
        "{%0,%1,%2,%3}, {%4,%5,%6,%7}, {%8,%9}, {%0,%1,%2,%3};"
        : "+f"(d[0]), "+f"(d[1]), "+f"(d[2]), "+f"(d[3])
        : "r"(a[0]), "r"(a[1]), "r"(a[2]), "r"(a[3]), "r"(b0), "r"(b1));
}

// ---------------------------------------------------------------------------
// Prep (coarse grid, 496 blocks):
//  blocks [0,304):   gather 8 seq rows each via masked_positions -> bf16 hi/lo
//  blocks [304,496): split W (3072 elems each) -> bf16 hi/lo
// Index dtype detection: int64 LE nonneg < 2^31 => odd 32-bit words all zero.
// ---------------------------------------------------------------------------
__global__ void __launch_bounds__(256)
prep_kernel(const float* __restrict__ seq, const int* __restrict__ mraw,
            const int* __restrict__ craw, const float* __restrict__ W)
{
    const int blk = blockIdx.x;
    const int tid = threadIdx.x;

    if (blk < 304) {
        __shared__ int nzm;
        if (tid == 0) nzm = 0;
        __syncthreads();
#pragma unroll
        for (int j = 0; j < 2; j++)
            if (mraw[2 * (tid + j * 256) + 1] != 0) atomicOr(&nzm, 1);  // 1024 w <= M_
        __syncthreads();
        const int m64 = (nzm == 0);
#pragma unroll
        for (int j = 0; j < 8; j++) {
            const int m = blk * 8 + j;
            const int pos = m64 ? mraw[2 * m] : mraw[m];
            const int b = m / P_;
            const float* src = seq + (size_t)(b * S_ + pos) * H_;
#pragma unroll
            for (int i = 0; i < 3; i++) {
                float v = src[tid + i * 256];
                __nv_bfloat16 hi = __float2bfloat16(v);
                __nv_bfloat16 lo = __float2bfloat16(v - __bfloat162float(hi));
                g_ahi[(size_t)m * H_ + tid + i * 256] = hi;
                g_alo[(size_t)m * H_ + tid + i * 256] = lo;
            }
        }
    } else {
        const int blk2 = blk - 304;          // 0..191
        const int base = blk2 * 3072;
#pragma unroll
        for (int i = 0; i < 12; i++) {
            int idx = base + i * 256 + tid;  // < 589824
            float v = W[idx];
            __nv_bfloat16 hi = __float2bfloat16(v);
            __nv_bfloat16 lo = __float2bfloat16(v - __bfloat162float(hi));
            g_whi[idx] = hi;
            g_wlo[idx] = lo;
        }
        if (blk2 == 0) {
            __shared__ int nzc;
            if (tid == 0) nzc = 0;
            __syncthreads();
            if (craw[2 * tid + 1] != 0) atomicOr(&nzc, 1);   // 512 w <= M_*K_
            __syncthreads();
            if (tid == 0) g_c64 = (nzc == 0);
        }
    }
}

// ---------------------------------------------------------------------------
// GEMM: bf16 mma.sync m16n8k16, 3-term hi/lo split (fp32-accurate).
// 64x96 tile/CTA, grid 8 x 38 = 304 CTAs -> 2 resident CTAs/SM (latency hiding).
// 8 warps = 4m x 2n, warp tile 16x48. K chunks of 32, cp.async double buffer.
// Static smem 47KB. Padded strides (A:40, B:104 bf16) -> conflict-free ldmatrix.
// ---------------------------------------------------------------------------
#define A_STR 40
#define B_STR 104

__global__ void __launch_bounds__(256)
gemm_mma_kernel(const float* __restrict__ bias)
{
    __shared__ __align__(16) __nv_bfloat16 sAhi[2][64][A_STR];
    __shared__ __align__(16) __nv_bfloat16 sAlo[2][64][A_STR];
    __shared__ __align__(16) __nv_bfloat16 sBhi[2][32][B_STR];
    __shared__ __align__(16) __nv_bfloat16 sBlo[2][32][B_STR];

    const int tid  = threadIdx.x;
    const int wid  = tid >> 5;
    const int lane = tid & 31;
    const int row0 = blockIdx.y * 64;
    const int col0 = blockIdx.x * 96;
    const int wm   = (wid >> 1) * 16;     // warp m offset (0..48)
    const int wn   = (wid & 1) * 48;      // warp n offset (0 or 48)

    // per-thread load slots
    const int ar = tid >> 2, ac = (tid & 3) * 8;          // A: 64 rows x 32 cols
    const int br0 = tid / 12, bc0 = (tid % 12) * 8;       // B slot 0 (tid<384 always)
    const int br1 = (tid + 256) / 12, bc1 = ((tid + 256) % 12) * 8;  // B slot 1 (tid<128)

    float acc[6][4];
#pragma unroll
    for (int i = 0; i < 6; i++)
#pragma unroll
        for (int q = 0; q < 4; q++) acc[i][q] = 0.f;

    auto load_chunk = [&](int c, int buf) {
        const int k0 = c * 32;
        cp16(smem_u32(&sAhi[buf][ar][ac]), g_ahi + (size_t)(row0 + ar) * H_ + k0 + ac);
        cp16(smem_u32(&sAlo[buf][ar][ac]), g_alo + (size_t)(row0 + ar) * H_ + k0 + ac);
        cp16(smem_u32(&sBhi[buf][br0][bc0]), g_whi + (size_t)(k0 + br0) * E_ + col0 + bc0);
        cp16(smem_u32(&sBlo[buf][br0][bc0]), g_wlo + (size_t)(k0 + br0) * E_ + col0 + bc0);
        if (tid < 128) {
            cp16(smem_u32(&sBhi[buf][br1][bc1]), g_whi + (size_t)(k0 + br1) * E_ + col0 + bc1);
            cp16(smem_u32(&sBlo[buf][br1][bc1]), g_wlo + (size_t)(k0 + br1) * E_ + col0 + bc1);
        }
    };

    load_chunk(0, 0);
    asm volatile("cp.async.commit_group;" ::: "memory");

    const int l15 = lane & 15, lh = lane >> 4;

    for (int c = 0; c < 24; ++c) {
        const int buf = c & 1;
        if (c + 1 < 24) {
            load_chunk(c + 1, 1 - buf);
            asm volatile("cp.async.commit_group;" ::: "memory");
            asm volatile("cp.async.wait_group 1;" ::: "memory");
        } else {
            asm volatile("cp.async.wait_group 0;" ::: "memory");
        }
        __syncthreads();

#pragma unroll
        for (int ks = 0; ks < 2; ++ks) {
            uint32_t bh[3][4], bl[3][4];
#pragma unroll
            for (int g = 0; g < 3; ++g) {
                uint32_t ba = smem_u32(&sBhi[buf][ks * 16 + l15][wn + g * 16 + lh * 8]);
                ldm_x4_t(bh[g], ba);
                uint32_t bb = smem_u32(&sBlo[buf][ks * 16 + l15][wn + g * 16 + lh * 8]);
                ldm_x4_t(bl[g], bb);
            }
            uint32_t ah[4], al[4];
            ldm_x4(ah, smem_u32(&sAhi[buf][wm + l15][ks * 16 + lh * 8]));
            ldm_x4(al, smem_u32(&sAlo[buf][wm + l15][ks * 16 + lh * 8]));
#pragma unroll
            for (int g = 0; g < 3; ++g) {
#pragma unroll
                for (int s = 0; s < 2; ++s) {
                    float* d = acc[g * 2 + s];
                    mma_bf16(d, ah, bh[g][s * 2], bh[g][s * 2 + 1]);
                    mma_bf16(d, ah, bl[g][s * 2], bl[g][s * 2 + 1]);
                    mma_bf16(d, al, bh[g][s * 2], bh[g][s * 2 + 1]);
                }
            }
        }
        __syncthreads();
    }

    // Epilogue: + bias, fp32 store
    const int lr = lane >> 2, lc2 = (lane & 3) * 2;
#pragma unroll
    for (int nf = 0; nf < 6; ++nf) {
        const int col = col0 + wn + nf * 8 + lc2;
        const float2 bb = *(const float2*)(bias + col);
        const int r0 = row0 + wm + lr;
        float2 v0, v1;
        v0.x = acc[nf][0] + bb.x;  v0.y = acc[nf][1] + bb.y;
        v1.x = acc[nf][2] + bb.x;  v1.y = acc[nf][3] + bb.y;
        *(float2*)(g_lm + (size_t)r0 * E_ + col)       = v0;
        *(float2*)(g_lm + (size_t)(r0 + 8) * E_ + col) = v1;
    }
}

// ---------------------------------------------------------------------------
// Logits: per-(b,p) LayerNorm (fused) + 64 candidate dots (proven version).
// ---------------------------------------------------------------------------
__global__ void __launch_bounds__(256)
logits_kernel(const int*   __restrict__ craw,
              const float* __restrict__ emb,
              const float* __restrict__ gamma,
              const float* __restrict__ beta,
              float* __restrict__ out)
{
    __shared__ __align__(16) float lm_s[E_];
    __shared__ float red[16];
    __shared__ float mu_s, rinv_s;

    const int bp   = blockIdx.x;
    const int tid  = threadIdx.x;
    const int wid  = tid >> 5;
    const int lane = tid & 31;
    const int c64  = g_c64;

    const float* row = g_lm + (size_t)bp * E_;
    float x0 = row[tid];
    float x1 = row[tid + 256];
    float x2 = row[tid + 512];

    float s  = x0 + x1 + x2;
    float sq = x0 * x0 + x1 * x1 + x2 * x2;
#pragma unroll
    for (int o = 16; o; o >>= 1) {
        s  += __shfl_xor_sync(0xffffffffu, s,  o);
        sq += __shfl_xor_sync(0xffffffffu, sq, o);
    }
    if (lane == 0) { red[wid] = s; red[wid + 8] = sq; }
    __syncthreads();
    if (tid == 0) {
        float S = 0.f, SQ = 0.f;
#pragma unroll
        for (int w = 0; w < 8; w++) { S += red[w]; SQ += red[w + 8]; }
        float mu  = S * (1.0f / E_);
        float var = SQ * (1.0f / E_) - mu * mu;
        mu_s   = mu;
        rinv_s = rsqrtf(var + 1e-12f);
    }
    __syncthreads();
    const float mu = mu_s, rinv = rinv_s;

    lm_s[tid]       = (x0 - mu) * rinv * gamma[tid]       + beta[tid];
    lm_s[tid + 256] = (x1 - mu) * rinv * gamma[tid + 256] + beta[tid + 256];
    lm_s[tid + 512] = (x2 - mu) * rinv * gamma[tid + 512] + beta[tid + 512];
    __syncthreads();

    const float4* lp = (const float4*)lm_s;

#pragma unroll
    for (int kk = 0; kk < 4; kk++) {
        int k  = wid * 8 + kk * 2;
        int i0 = bp * K_ + k;
        int c0 = c64 ? craw[2 * i0]     : craw[i0];
        int c1 = c64 ? craw[2 * i0 + 2] : craw[i0 + 1];
        const float4* e0 = (const float4*)(emb + (size_t)c0 * E_);
        const float4* e1 = (const float4*)(emb + (size_t)c1 * E_);
        float a0 = 0.f, a1 = 0.f;
#pragma unroll
        for (int j = 0; j < 6; j++) {
            float4 l  = lp[j * 32 + lane];
            float4 v0 = e0[j * 32 + lane];
            float4 v1 = e1[j * 32 + lane];
            a0 += v0.x * l.x + v0.y * l.y + v0.z * l.z + v0.w * l.w;
            a1 += v1.x * l.x + v1.y * l.y + v1.z * l.z + v1.w * l.w;
        }
#pragma unroll
        for (int o = 16; o; o >>= 1) {
            a0 += __shfl_xor_sync(0xffffffffu, a0, o);
            a1 += __shfl_xor_sync(0xffffffffu, a1, o);
        }
        if (lane == 0) {
            out[i0]     = a0;
            out[i0 + 1] = a1;
        }
    }
}

// ---------------------------------------------------------------------------
extern "C" void kernel_launch(void* const* d_in, const int* in_sizes, int n_in,
                              void* d_out, int out_size)
{
    const float* seq   = (const float*)d_in[0];
    const int*   mraw  = (const int*)d_in[1];
    const int*   craw  = (const int*)d_in[2];
    const float* emb   = (const float*)d_in[3];
    const float* W     = (const float*)d_in[4];
    const float* bias  = (const float*)d_in[5];
    const float* gamma = (const float*)d_in[6];
    const float* beta  = (const float*)d_in[7];
    float*       out   = (float*)d_out;

    prep_kernel<<<496, 256>>>(seq, mraw, craw, W);
    dim3 g1(E_ / 96, M_ / 64);   // 8 x 38 = 304 CTAs
    gemm_mma_kernel<<<g1, 256>>>(bias);
    logits_kernel<<<M_, 256>>>(craw, emb, gamma, beta, out);
}